// round 9
// baseline (speedup 1.0000x reference)
#include <cuda_runtime.h>
#include <cstdint>

#define BB 128
#define CC 32
#define LL 4096
#define LT 16           // l positions per CTA
#define BCH 8           // batch rows per chunk
#define NCH 4           // chunks per CTA (32 b per CTA)
#define BSPLIT 4        // b-splits across CTAs
#define THREADS 512     // 16 warps, warp w handles l = l0 + w

#define XS_FLOATS (BCH * LT * CC)     // 4096 floats = 16 KB
#define OS_PAD 17
#define OS_FLOATS (BCH * CC * OS_PAD) // 4352 floats = 17 KB

__device__ __forceinline__ unsigned long long pack_f32x2(float lo, float hi) {
    unsigned long long r;
    asm("mov.b64 %0, {%1, %2};" : "=l"(r) : "r"(__float_as_uint(lo)), "r"(__float_as_uint(hi)));
    return r;
}
__device__ __forceinline__ void unpack_f32x2(unsigned long long v, float& lo, float& hi) {
    unsigned int a, b;
    asm("mov.b64 {%0, %1}, %2;" : "=r"(a), "=r"(b) : "l"(v));
    lo = __uint_as_float(a);
    hi = __uint_as_float(b);
}
__device__ __forceinline__ void fma2(unsigned long long& d, unsigned long long a,
                                     unsigned long long b, unsigned long long c) {
    asm("fma.rn.f32x2 %0, %1, %2, %3;" : "=l"(d) : "l"(a), "l"(b), "l"(c));
}
__device__ __forceinline__ unsigned long long add2(unsigned long long a, unsigned long long b) {
    unsigned long long d;
    asm("add.rn.f32x2 %0, %1, %2;" : "=l"(d) : "l"(a), "l"(b));
    return d;
}

__global__ void __launch_bounds__(THREADS, 2)
dyna_dec_kernel(const float* __restrict__ x, const float* __restrict__ weight,
                const float* __restrict__ bias, float* __restrict__ out) {
    __shared__ __align__(16) float x_s[XS_FLOATS];
    __shared__ __align__(16) float o_s[OS_FLOATS];

    const int tid  = threadIdx.x;
    const int w    = tid >> 5;       // warp index = local l
    const int lane = tid & 31;       // output channel d (compute phase)
    const int b0   = blockIdx.x * (BCH * NCH);   // b-split minor -> weight L2 reuse
    const int l0   = blockIdx.y * LT;
    const int lg   = l0 + w;

    // ---- Per-warp weight column: W2[p] = {W[lg][2p][lane], W[lg][2p+1][lane]} ----
    unsigned long long W2[CC / 2];
    {
        const float* wp = weight + (size_t)lg * CC * CC + lane;
        #pragma unroll
        for (int p = 0; p < CC / 2; p++) {
            float a = __ldg(wp + (2 * p) * CC);
            float b = __ldg(wp + (2 * p + 1) * CC);
            W2[p] = pack_f32x2(a, b);
        }
    }
    const float bi = __ldg(bias + lg * CC + lane);

    const int swc = (w >> 1) & 6;    // compute-side x_s chunk swizzle for l = w
    const int seg = w >> 2, j = w & 3;

    float4 pf0, pf1;                 // prefetch registers (2 tasks/thread)

    // ---------- prologue: prefetch chunk 0 ----------
    {
        int t0 = tid,           ls0 = t0 & 3, r0 = t0 >> 2;
        int t1 = THREADS + tid, ls1 = t1 & 3, r1 = t1 >> 2;
        pf0 = *(const float4*)(x + ((size_t)((b0 + (r0 >> 5)) * CC + (r0 & 31))) * LL + l0 + 4 * ls0);
        pf1 = *(const float4*)(x + ((size_t)((b0 + (r1 >> 5)) * CC + (r1 & 31))) * LL + l0 + 4 * ls1);
    }

    for (int ch = 0; ch < NCH; ch++) {
        // ---- stage prefetched chunk into x_s (swizzled, conflict-free STS) ----
        // Safe without a leading sync: the sync after compute(ch-1) guarantees
        // all x_s reads of the previous chunk completed before the out-pass,
        // and stage touches only x_s while out-pass touches only o_s.
        #pragma unroll
        for (int it = 0; it < 2; it++) {
            int t = it * THREADS + tid;
            int lseg = t & 3;
            int r = t >> 2;
            int b = r >> 5, c = r & 31;
            int slot = ((c >> 2) ^ (2 * lseg)) & 7;
            float* dst = x_s + b * (LT * CC) + (4 * lseg) * CC + slot * 4 + (c & 3);
            float4 v = it == 0 ? pf0 : pf1;
            dst[0 * CC] = v.x; dst[1 * CC] = v.y; dst[2 * CC] = v.z; dst[3 * CC] = v.w;
        }

        // ---- prefetch next chunk (LDG latency hidden behind compute) ----
        if (ch + 1 < NCH) {
            int bc = b0 + (ch + 1) * BCH;
            int t0 = tid,           ls0 = t0 & 3, r0 = t0 >> 2;
            int t1 = THREADS + tid, ls1 = t1 & 3, r1 = t1 >> 2;
            pf0 = *(const float4*)(x + ((size_t)((bc + (r0 >> 5)) * CC + (r0 & 31))) * LL + l0 + 4 * ls0);
            pf1 = *(const float4*)(x + ((size_t)((bc + (r1 >> 5)) * CC + (r1 & 31))) * LL + l0 + 4 * ls1);
        }
        __syncthreads();  // x_s ready; also fences out-pass(ch-1) reads of o_s

        // ---- compute: warp w handles l = l0 + w; lane = d; 4 accumulators ----
        #pragma unroll
        for (int b = 0; b < BCH; b++) {
            const char* base = (const char*)(x_s + b * (LT * CC) + w * CC);
            unsigned long long a0 = 0ull, a1 = 0ull, a2 = 0ull, a3 = 0ull;
            #pragma unroll
            for (int u = 0; u < 8; u += 2) {
                ulonglong2 v0 = *(const ulonglong2*)(base + ((( u      ^ swc) & 7) << 4));
                ulonglong2 v1 = *(const ulonglong2*)(base + ((((u + 1) ^ swc) & 7) << 4));
                fma2(a0, v0.x, W2[2 * u + 0], a0);
                fma2(a1, v0.y, W2[2 * u + 1], a1);
                fma2(a2, v1.x, W2[2 * u + 2], a2);
                fma2(a3, v1.y, W2[2 * u + 3], a3);
            }
            unsigned long long s = add2(add2(a0, a1), add2(a2, a3));
            float lo, hi;
            unpack_f32x2(s, lo, hi);
            int row = b * CC + lane;
            int segp = (seg + ((row >> 1) & 2)) & 3;          // additive seg swizzle
            o_s[row * OS_PAD + 4 * segp + j] = lo + hi + bi;  // conflict-free STS
        }
        __syncthreads();  // o_s ready; also fences compute's x_s reads for next stage

        // ---- output pass: gather rows from o_s, vectorized STG ----
        #pragma unroll
        for (int it = 0; it < 2; it++) {
            int t = it * THREADS + tid;
            int s = t & 3;
            int r = t >> 2;                 // row = b*32 + d
            int b = r >> 5, d = r & 31;
            int segp = (s + ((r >> 1) & 2)) & 3;
            const float* src = o_s + r * OS_PAD + 4 * segp;
            float4 v;
            v.x = src[0]; v.y = src[1]; v.z = src[2]; v.w = src[3];
            *(float4*)(out + ((size_t)((b0 + ch * BCH + b) * CC + d)) * LL + l0 + 4 * s) = v;
        }
    }
}

extern "C" void kernel_launch(void* const* d_in, const int* in_sizes, int n_in,
                              void* d_out, int out_size) {
    const float* x      = (const float*)d_in[0];
    // d_in[1] = px, unused by the reference
    const float* weight = (const float*)d_in[2];
    const float* bias   = (const float*)d_in[3];
    float* out          = (float*)d_out;

    dim3 grid(BSPLIT, LL / LT);   // (4, 256): weight-sharing siblings wave-adjacent
    dim3 block(THREADS);
    dyna_dec_kernel<<<grid, block>>>(x, weight, bias, out);
}

// round 11
// speedup vs baseline: 1.6888x; 1.6888x over previous
#include <cuda_runtime.h>
#include <cstdint>

#define LL 4096
#define CC 32
#define LT 8            // l per CTA; warp w owns l0+w
#define THREADS 256     // 8 warps
#define BCH 16          // b rows per chunk = one m16 M-tile
#define NCH 4           // chunks per CTA (64 b)
#define BSPLIT 2        // b halves across CTAs

#define XPLANE 512      // x_s l-plane: 16 b x 32 c (tf32 bits)
#define OPITCH 21       // o_s d-pitch (gcd(21,32)=1 -> conflict-free gather)
#define OPLANE (CC * OPITCH)  // 672 floats per l-plane

__device__ __forceinline__ uint32_t f2tf32(float f) {
    uint32_t r;
    asm("cvt.rna.tf32.f32 %0, %1;" : "=r"(r) : "f"(f));
    return r;
}

__device__ __forceinline__ void mma_tf32(
    float& d0, float& d1, float& d2, float& d3,
    uint32_t a0, uint32_t a1, uint32_t a2, uint32_t a3,
    uint32_t b0, uint32_t b1,
    float c0, float c1, float c2, float c3) {
    asm("mma.sync.aligned.m16n8k8.row.col.f32.tf32.tf32.f32 "
        "{%0,%1,%2,%3}, {%4,%5,%6,%7}, {%8,%9}, {%10,%11,%12,%13};"
        : "=f"(d0), "=f"(d1), "=f"(d2), "=f"(d3)
        : "r"(a0), "r"(a1), "r"(a2), "r"(a3), "r"(b0), "r"(b1),
          "f"(c0), "f"(c1), "f"(c2), "f"(c3));
}

__global__ void __launch_bounds__(THREADS, 3)
dyna_dec_kernel(const float* __restrict__ x, const float* __restrict__ weight,
                const float* __restrict__ bias, float* __restrict__ out) {
    __shared__ __align__(16) uint32_t x_s[LT * XPLANE];   // 16 KB
    __shared__ __align__(16) float    o_s[LT * OPLANE];   // 21 KB

    const int tid  = threadIdx.x;
    const int w    = tid >> 5;       // warp = local l
    const int lane = tid & 31;
    const int q    = lane & 3;       // k-in-tile (A col / B row)
    const int p    = lane >> 2;      // m row / n col within fragments
    const int l0   = blockIdx.x * LT;
    const int b0   = blockIdx.y * (BCH * NCH);
    const int lg   = l0 + w;

    // ---- B fragments: bf[kt][nt] = {W[8kt+q][8nt+p], W[8kt+q+4][8nt+p]} ----
    uint32_t bf[4][4][2];
    float    bb[4][2];               // bias pairs per ntile: cols 8nt+2q, +1
    {
        const float* wp = weight + (size_t)lg * CC * CC;
        #pragma unroll
        for (int nt = 0; nt < 4; nt++) {
            #pragma unroll
            for (int kt = 0; kt < 4; kt++) {
                bf[kt][nt][0] = f2tf32(__ldg(wp + (8 * kt + q) * CC + 8 * nt + p));
                bf[kt][nt][1] = f2tf32(__ldg(wp + (8 * kt + q + 4) * CC + 8 * nt + p));
            }
            float2 bv = *(const float2*)(bias + (size_t)lg * CC + 8 * nt + 2 * q);
            bb[nt][0] = bv.x;
            bb[nt][1] = bv.y;
        }
    }

    for (int ch = 0; ch < NCH; ch++) {
        const int cb = b0 + ch * BCH;

        // ---- stage: x[cb..cb+15, c, l0..l0+7] -> x_s (perm+rot, tf32) ----
        #pragma unroll
        for (int it = 0; it < 4; it++) {
            int i = it * THREADS + tid;
            int s = i & 1, r = i >> 1;          // lanes pair on s: 16 lines/LDG
            int bl = r >> 5, c = r & 31;
            float4 v = *(const float4*)(x + ((size_t)(cb + bl) * CC + c) * LL + l0 + 4 * s);
            // perm(c): c = 8kt+4h+q -> pos 8q+2kt+h ; then rotate by 4*(bl&7)
            int e = ((((c & 3) << 3) | ((c >> 3) << 1) | ((c >> 2) & 1)) + 4 * (bl & 7)) & 31;
            uint32_t* dst = x_s + bl * CC + e;
            dst[(4 * s + 0) * XPLANE] = f2tf32(v.x);
            dst[(4 * s + 1) * XPLANE] = f2tf32(v.y);
            dst[(4 * s + 2) * XPLANE] = f2tf32(v.z);
            dst[(4 * s + 3) * XPLANE] = f2tf32(v.w);
        }
        __syncthreads();   // x_s ready; also fences out-pass(ch-1) o_s reads

        // ---- compute: 4x LDS.128 A-frags + 16 mma (bias in C operand) ----
        {
            const uint32_t* xp = x_s + w * XPLANE;
            const int rot = 4 * p;               // rows r0=p, r1=p+8: same rot
            uint4 v00 = *(const uint4*)(xp + p * CC + ((8 * q + rot) & 31));
            uint4 v01 = *(const uint4*)(xp + p * CC + ((8 * q + 4 + rot) & 31));
            uint4 v10 = *(const uint4*)(xp + (p + 8) * CC + ((8 * q + rot) & 31));
            uint4 v11 = *(const uint4*)(xp + (p + 8) * CC + ((8 * q + 4 + rot) & 31));

            float acc[4][4];
            #pragma unroll
            for (int nt = 0; nt < 4; nt++) {
                acc[nt][0] = bb[nt][0]; acc[nt][1] = bb[nt][1];
                acc[nt][2] = bb[nt][0]; acc[nt][3] = bb[nt][1];
            }
            #pragma unroll
            for (int nt = 0; nt < 4; nt++) {
                mma_tf32(acc[nt][0], acc[nt][1], acc[nt][2], acc[nt][3],
                         v00.x, v10.x, v00.y, v10.y, bf[0][nt][0], bf[0][nt][1],
                         acc[nt][0], acc[nt][1], acc[nt][2], acc[nt][3]);
                mma_tf32(acc[nt][0], acc[nt][1], acc[nt][2], acc[nt][3],
                         v00.z, v10.z, v00.w, v10.w, bf[1][nt][0], bf[1][nt][1],
                         acc[nt][0], acc[nt][1], acc[nt][2], acc[nt][3]);
                mma_tf32(acc[nt][0], acc[nt][1], acc[nt][2], acc[nt][3],
                         v01.x, v11.x, v01.y, v11.y, bf[2][nt][0], bf[2][nt][1],
                         acc[nt][0], acc[nt][1], acc[nt][2], acc[nt][3]);
                mma_tf32(acc[nt][0], acc[nt][1], acc[nt][2], acc[nt][3],
                         v01.z, v11.z, v01.w, v11.w, bf[3][nt][0], bf[3][nt][1],
                         acc[nt][0], acc[nt][1], acc[nt][2], acc[nt][3]);
            }
            // D -> o_s[l][d*21 + bl]
            float* op = o_s + w * OPLANE;
            #pragma unroll
            for (int nt = 0; nt < 4; nt++) {
                int d = 8 * nt + 2 * q;
                op[d * OPITCH + p]           = acc[nt][0];
                op[(d + 1) * OPITCH + p]     = acc[nt][1];
                op[d * OPITCH + p + 8]       = acc[nt][2];
                op[(d + 1) * OPITCH + p + 8] = acc[nt][3];
            }
        }
        __syncthreads();   // o_s ready

        // ---- out-pass: gather 8 l per (b,d), paired-lane STG.128 ----
        #pragma unroll
        for (int it = 0; it < 4; it++) {
            int i = it * THREADS + tid;
            int s = i & 1, r = i >> 1;
            int d = r & 31, bl = r >> 5;
            const float* src = o_s + d * OPITCH + bl;
            float4 v;
            v.x = src[(4 * s + 0) * OPLANE];
            v.y = src[(4 * s + 1) * OPLANE];
            v.z = src[(4 * s + 2) * OPLANE];
            v.w = src[(4 * s + 3) * OPLANE];
            *(float4*)(out + ((size_t)(cb + bl) * CC + d) * LL + l0 + 4 * s) = v;
        }
        // no extra sync: next stage writes x_s only (disjoint from o_s); next
        // compute's o_s writes are fenced by the stage-sync.
    }
}

extern "C" void kernel_launch(void* const* d_in, const int* in_sizes, int n_in,
                              void* d_out, int out_size) {
    const float* x      = (const float*)d_in[0];
    // d_in[1] = px, unused by the reference
    const float* weight = (const float*)d_in[2];
    const float* bias   = (const float*)d_in[3];
    float* out          = (float*)d_out;

    dim3 grid(LL / LT, BSPLIT);   // (512, 2) = 1024 CTAs
    dim3 block(THREADS);
    dyna_dec_kernel<<<grid, block>>>(x, weight, bias, out);
}